// round 1
// baseline (speedup 1.0000x reference)
#include <cuda_runtime.h>

// Random_RNN two-hop sparse propagation.
//   Hop1: acc1[j][b] = sum over in-edges(dst=j) of w * x[b][src]        (j in assoc space, 4096)
//   Hop2: out[b][o]  = sum over ass-edges(dst=out0+o) of w * acc1[src][b]
// Only ass-edges whose dst is an OUTPUT node matter (acc2 at assoc nodes is never read)
// -> filter ~891K edges down to ~52K.
// All per-launch state lives in __device__ globals (no allocation). CSC built fresh
// every launch (counters zeroed in k_init), so replays are deterministic.

#define B      128
#define IN_F   256
#define N_ASS  4096
#define OUT_F  256
#define ASS0   256
#define OUT0   (IN_F + N_ASS)   // 4352
#define MAX_E  131072           // >> expected ~52.5K for either CSC edge list

__device__ float g_xT[IN_F * B];       // x transposed: [src][b], 128 KB (L2/L1 resident)
__device__ float g_acc1[N_ASS * B];    // assoc activations, 2 MB (L2 resident)
__device__ int   g_h1_cnt[N_ASS];
__device__ int   g_h1_off[N_ASS + 1];
__device__ int   g_h1_cur[N_ASS];
__device__ int   g_h2_cnt[OUT_F];
__device__ int   g_h2_off[OUT_F + 1];
__device__ int   g_h2_cur[OUT_F];
__device__ int   g_e1_src[MAX_E];      // hop1 CSC payload
__device__ float g_e1_w[MAX_E];
__device__ int   g_e2_src[MAX_E];      // hop2 (filtered) CSC payload, src in [0, N_ASS)
__device__ float g_e2_w[MAX_E];

// ---------------------------------------------------------------- init
__global__ void k_init(const float* __restrict__ x) {
    int i  = blockIdx.x * blockDim.x + threadIdx.x;
    int nt = gridDim.x * blockDim.x;
    // transpose x [B][IN_F] -> xT [IN_F][B] (coalesced read)
    for (int idx = i; idx < IN_F * B; idx += nt) {
        int b = idx / IN_F, s = idx % IN_F;
        g_xT[s * B + b] = x[idx];
    }
    for (int idx = i; idx < N_ASS; idx += nt) g_h1_cnt[idx] = 0;
    for (int idx = i; idx < OUT_F; idx += nt) g_h2_cnt[idx] = 0;
}

// ---------------------------------------------------------------- histograms
__global__ void k_hist(const int* __restrict__ in_dst, int E_in,
                       const int* __restrict__ a_dst, int E_ass) {
    __shared__ int sh2[OUT_F];
    int tid = threadIdx.x;
    for (int k = tid; k < OUT_F; k += blockDim.x) sh2[k] = 0;
    __syncthreads();
    int i  = blockIdx.x * blockDim.x + tid;
    int nt = gridDim.x * blockDim.x;
    // hop1 bins: 4096, ~13 hits each -> global atomics fine
    for (int e = i; e < E_in; e += nt)
        atomicAdd(&g_h1_cnt[in_dst[e] - ASS0], 1);
    // hop2 bins: 256, ~205 hits each -> stage in smem, flush once per CTA
    for (int e = i; e < E_ass; e += nt) {
        int d = a_dst[e];
        if (d >= OUT0) atomicAdd(&sh2[d - OUT0], 1);
    }
    __syncthreads();
    for (int k = tid; k < OUT_F; k += blockDim.x)
        if (sh2[k]) atomicAdd(&g_h2_cnt[k], sh2[k]);
}

// ---------------------------------------------------------------- prefix scan (2 blocks)
__global__ void k_prefix() {
    const int n  = (blockIdx.x == 0) ? N_ASS : OUT_F;
    int* cnt = (blockIdx.x == 0) ? g_h1_cnt : g_h2_cnt;
    int* off = (blockIdx.x == 0) ? g_h1_off : g_h2_off;
    int* cur = (blockIdx.x == 0) ? g_h1_cur : g_h2_cur;
    __shared__ int wsum[32];
    int t = threadIdx.x;                 // 1024 threads
    const int ITEMS = 4;                 // 1024*4 = 4096 covers both sizes
    int base_i = t * ITEMS;
    int v[ITEMS];
    int local = 0;
#pragma unroll
    for (int k = 0; k < ITEMS; k++) {
        int idx = base_i + k;
        v[k] = (idx < n) ? cnt[idx] : 0;
        local += v[k];
    }
    int lane = t & 31, warp = t >> 5;
    int incl = local;
#pragma unroll
    for (int d = 1; d < 32; d <<= 1) {
        int y = __shfl_up_sync(0xffffffffu, incl, d);
        if (lane >= d) incl += y;
    }
    if (lane == 31) wsum[warp] = incl;
    __syncthreads();
    if (warp == 0) {
        int wv = wsum[lane];
        int wincl = wv;
#pragma unroll
        for (int d = 1; d < 32; d <<= 1) {
            int y = __shfl_up_sync(0xffffffffu, wincl, d);
            if (lane >= d) wincl += y;
        }
        wsum[lane] = wincl - wv;         // exclusive warp offsets
    }
    __syncthreads();
    int run = (incl - local) + wsum[warp];  // thread-exclusive base
#pragma unroll
    for (int k = 0; k < ITEMS; k++) {
        int idx = base_i + k;
        if (idx < n) { off[idx] = run; cur[idx] = run; }
        run += v[k];
    }
    if (t == blockDim.x - 1) off[n] = run;  // grand total
}

// ---------------------------------------------------------------- CSC fill
__global__ void k_fill(const int* __restrict__ in_src, const int* __restrict__ in_dst,
                       const float* __restrict__ in_w, int E_in,
                       const int* __restrict__ a_src, const int* __restrict__ a_dst,
                       const float* __restrict__ a_w, int E_ass) {
    int i  = blockIdx.x * blockDim.x + threadIdx.x;
    int nt = gridDim.x * blockDim.x;
    for (int e = i; e < E_in; e += nt) {
        int d   = in_dst[e] - ASS0;
        int pos = atomicAdd(&g_h1_cur[d], 1);
        g_e1_src[pos] = in_src[e];       // input index 0..255
        g_e1_w[pos]   = in_w[e];
    }
    for (int e = i; e < E_ass; e += nt) {
        int d = a_dst[e];
        if (d >= OUT0) {
            int pos = atomicAdd(&g_h2_cur[d - OUT0], 1);
            g_e2_src[pos] = a_src[e] - ASS0;  // assoc index 0..4095
            g_e2_w[pos]   = a_w[e];
        }
    }
}

// ---------------------------------------------------------------- hop 1 gather
// one block per assoc node, one thread per batch element; atomic-free
__global__ void k_hop1() {
    int j = blockIdx.x;
    int b = threadIdx.x;
    int s0 = g_h1_off[j], s1 = g_h1_off[j + 1];
    float r = 0.f;
    int e = s0;
    for (; e + 4 <= s1; e += 4) {        // 4-wide: batch index loads -> MLP 4
        int   a0 = g_e1_src[e],     a1 = g_e1_src[e + 1];
        int   a2 = g_e1_src[e + 2], a3 = g_e1_src[e + 3];
        float w0 = g_e1_w[e],       w1 = g_e1_w[e + 1];
        float w2 = g_e1_w[e + 2],   w3 = g_e1_w[e + 3];
        r += w0 * g_xT[a0 * B + b];
        r += w1 * g_xT[a1 * B + b];
        r += w2 * g_xT[a2 * B + b];
        r += w3 * g_xT[a3 * B + b];
    }
    for (; e < s1; e++) r += g_e1_w[e] * g_xT[g_e1_src[e] * B + b];
    g_acc1[j * B + b] = r;               // every row written -> no pre-zero needed
}

// ---------------------------------------------------------------- hop 2 gather
// one block per output node, one thread per batch element; 8-wide unroll for MLP
__global__ void k_hop2(float* __restrict__ out) {
    int o = blockIdx.x;
    int b = threadIdx.x;
    int s0 = g_h2_off[o], s1 = g_h2_off[o + 1];
    float r = 0.f;
    int e = s0;
    for (; e + 8 <= s1; e += 8) {
        int a[8]; float w[8];
#pragma unroll
        for (int k = 0; k < 8; k++) { a[k] = g_e2_src[e + k]; w[k] = g_e2_w[e + k]; }
#pragma unroll
        for (int k = 0; k < 8; k++) r += w[k] * g_acc1[a[k] * B + b];
    }
    for (; e < s1; e++) r += g_e2_w[e] * g_acc1[g_e2_src[e] * B + b];
    out[b * OUT_F + o] = r;              // [B, OUT_F] row-major, matches reference .T
}

// ---------------------------------------------------------------- launch
extern "C" void kernel_launch(void* const* d_in, const int* in_sizes, int n_in,
                              void* d_out, int out_size) {
    const float* x      = (const float*)d_in[0];
    const float* in_w   = (const float*)d_in[1];
    const float* a_w    = (const float*)d_in[2];
    const int*   in_src = (const int*)d_in[3];
    const int*   in_dst = (const int*)d_in[4];
    const int*   a_src  = (const int*)d_in[5];
    const int*   a_dst  = (const int*)d_in[6];
    int E_in  = in_sizes[1];   // len(input_weights)
    int E_ass = in_sizes[2];   // len(associative_weights)
    float* out = (float*)d_out;

    k_init  <<<64, 256>>>(x);
    k_hist  <<<256, 256>>>(in_dst, E_in, a_dst, E_ass);
    k_prefix<<<2, 1024>>>();
    k_fill  <<<256, 256>>>(in_src, in_dst, in_w, E_in, a_src, a_dst, a_w, E_ass);
    k_hop1  <<<N_ASS, B>>>();
    k_hop2  <<<OUT_F, B>>>(out);
}